// round 14
// baseline (speedup 1.0000x reference)
#include <cuda_runtime.h>
#include <cuda_bf16.h>
#include <stdint.h>

#define NTILES 4352
#define TEQ    4096
#define TIB    4224
#define NU     0.0031830988618379067154f
typedef unsigned long long u64;

__device__ uint2 g_wfH[12288];
__device__ uint2 g_wfL[12288];

__device__ __forceinline__ uint32_t pkbf(float lo, float hi) {
    uint32_t r; asm("cvt.rn.bf16x2.f32 %0, %1, %2;" : "=r"(r) : "f"(hi), "f"(lo)); return r;
}
__device__ __forceinline__ void split2(float v0, float v1, uint32_t& h, uint32_t& l) {
    h = pkbf(v0, v1);
    float h0 = __uint_as_float(h << 16);
    float h1 = __uint_as_float(h & 0xffff0000u);
    l = pkbf(v0 - h0, v1 - h1);
}
__device__ __forceinline__ u64 pk2(float lo, float hi) {
    u64 r; asm("mov.b64 %0, {%1, %2};" : "=l"(r) : "f"(lo), "f"(hi)); return r;
}
__device__ __forceinline__ void upk2(u64 v, float& lo, float& hi) {
    asm("mov.b64 {%0, %1}, %2;" : "=f"(lo), "=f"(hi) : "l"(v));
}
__device__ __forceinline__ void fma2(u64& d, u64 a, u64 b) {
    asm("fma.rn.f32x2 %0, %1, %2, %0;" : "+l"(d) : "l"(a), "l"(b));
}
__device__ __forceinline__ float tanhf_fast(float z) {
    float e = __expf(2.0f * z);
    return __fdividef(e - 1.0f, e + 1.0f);
}
__device__ __forceinline__ void mma16816(float* c, const uint32_t* a, uint32_t b0, uint32_t b1) {
    asm volatile(
        "mma.sync.aligned.m16n8k16.row.col.f32.bf16.bf16.f32 "
        "{%0,%1,%2,%3}, {%4,%5,%6,%7}, {%8,%9}, {%0,%1,%2,%3};"
        : "+f"(c[0]), "+f"(c[1]), "+f"(c[2]), "+f"(c[3])
        : "r"(a[0]), "r"(a[1]), "r"(a[2]), "r"(a[3]), "r"(b0), "r"(b1));
}

__global__ void prep_kernel(const float* __restrict__ W1,
                            const float* __restrict__ W2,
                            const float* __restrict__ W3)
{
    const int gt = blockIdx.x * blockDim.x + threadIdx.x;
    const int lane = gt & 31, wi = gt >> 5;
    const int nt = wi & 15, ks = (wi >> 4) & 7, l = wi >> 7;
    const float* W = (l == 0) ? W1 : (l == 1) ? W2 : W3;
    const int j = nt * 8 + (lane >> 2), k0 = ks * 16 + 2 * (lane & 3);
    uint32_t h0, l0, h1, l1;
    split2(W[k0 * 128 + j], W[(k0 + 1) * 128 + j], h0, l0);
    split2(W[(k0 + 8) * 128 + j], W[(k0 + 9) * 128 + j], h1, l1);
    g_wfH[wi * 32 + lane] = make_uint2(h0, h1);
    g_wfL[wi * 32 + lane] = make_uint2(l0, l1);
}

// smem map
#define OFF_STA  98304     // float [32][132]
#define OFF_STT  115200    // float [32][132]
#define OFF_STX  132096    // u64 [128][18]
#define OFF_STXX 150528    // u64 [128][18]
#define OFF_ZX   168960    // u64 [2][32][32]
#define OFF_OUT  185344    // 192 floats
#define SMEM_BYTES 186112

extern __shared__ char smem_raw[];

__global__ __launch_bounds__(384, 1)
void pinn_hy(const float* __restrict__ tx_eq, const float* __restrict__ tx_init,
             const float* __restrict__ tx_bnd,
             const float* __restrict__ W0, const float* __restrict__ b0,
             const float* __restrict__ W1, const float* __restrict__ b1,
             const float* __restrict__ W2, const float* __restrict__ b2,
             const float* __restrict__ W3, const float* __restrict__ b3,
             const float* __restrict__ W4, const float* __restrict__ b4,
             float* __restrict__ out)
{
    uint2* whS  = (uint2*)smem_raw;
    float* st_a = (float*)(smem_raw + OFF_STA);
    float* st_t = (float*)(smem_raw + OFF_STT);
    u64*  st_x  = (u64*)(smem_raw + OFF_STX);
    u64*  st_xx = (u64*)(smem_raw + OFF_STXX);
    float* fx   = (float*)st_x;
    float* fxx  = (float*)st_xx;
    u64*  zxscr = (u64*)(smem_raw + OFF_ZX);
    float* sout = (float*)(smem_raw + OFF_OUT);

    const int tid  = threadIdx.x;
    const int lane = tid & 31;
    const int wid  = tid >> 5;       // 0..11
    const bool isT = wid < 8;
    const int ts  = wid >> 2;        // tensor state: 0=a 1=t (valid when isT)
    const int sub = wid & 3;
    const int R   = sub & 1;
    const int nh  = sub >> 1;
    const int q   = lane & 3;
    const int ra  = 16 * R + (lane >> 2), rb = ra + 8;
    const int sw  = wid - 8;
    const int ss  = (sw >> 1) & 1;   // simt state: 0=x 1=xx
    const int h   = sw & 1;          // point half
    int jm[4];
    jm[0] = 2 * lane; jm[1] = 2 * lane + 1;
    jm[2] = 64 + 2 * lane; jm[3] = 65 + 2 * lane;

    for (int i = tid; i < 12288; i += 384) whS[i] = g_wfH[i];
    const float b4v = __ldg(b4);
    __syncthreads();

    for (int tile = blockIdx.x; tile < NTILES; tile += gridDim.x) {
        const float2* src;
        if (tile < TEQ)      src = (const float2*)tx_eq  + tile * 32;
        else if (tile < TIB) src = (const float2*)tx_init + (tile - TEQ) * 32;
        else                 src = (const float2*)tx_bnd  + (tile - TIB) * 32;

        // ---- layer 0 seeds into all 4 state buffers ----
        for (int idx = tid; idx < 2048; idx += 384) {
            const int pt = idx >> 6, jp = idx & 63;
            const float2 P = __ldg(src + pt);
            float av[2], tv[2], xv[2], xxv[2];
            #pragma unroll
            for (int m = 0; m < 2; m++) {
                const int j = 2 * jp + m;
                const float wt = __ldg(W0 + j);
                const float wx = __ldg(W0 + 128 + j);
                const float bb = __ldg(b0 + j);
                const float z = fmaf(wt, P.x, fmaf(wx, P.y, bb));
                const float a = tanhf_fast(z);
                const float p = 1.0f - a * a;
                av[m] = a; tv[m] = p * wt; xv[m] = p * wx;
                xxv[m] = -2.0f * a * xv[m] * wx;
            }
            *(float2*)(st_a + pt * 132 + 2 * jp) = make_float2(av[0], av[1]);
            *(float2*)(st_t + pt * 132 + 2 * jp) = make_float2(tv[0], tv[1]);
            const int ptp = pt >> 1, hf = pt & 1;
            fx [(2*jp) * 36 + 2*ptp + hf] = xv[0];
            fx [(2*jp+1) * 36 + 2*ptp + hf] = xv[1];
            fxx[(2*jp) * 36 + 2*ptp + hf] = xxv[0];
            fxx[(2*jp+1) * 36 + 2*ptp + hf] = xxv[1];
        }
        __syncthreads();

        // ---- 3 hidden layers ----
        #pragma unroll 1
        for (int l = 0; l < 3; l++) {
            const bool last = (l == 2);
            float c[8][4];
            u64 acc[4][8];
            if (isT) {
                const float* stS = ts ? st_t : st_a;
                #pragma unroll
                for (int nt = 0; nt < 8; nt++) {
                    c[nt][0] = 0.f; c[nt][1] = 0.f; c[nt][2] = 0.f; c[nt][3] = 0.f;
                }
                const uint2* bh  = whS + l * 4096 + lane;
                const uint2* blg = g_wfL + l * 4096 + lane;
                #pragma unroll
                for (int ks = 0; ks < 8; ks++) {
                    uint2 BL[8], BH[8];
                    #pragma unroll
                    for (int nt = 0; nt < 8; nt++)
                        BL[nt] = __ldg(blg + (ks * 16 + 8 * nh + nt) * 32);
                    #pragma unroll
                    for (int nt = 0; nt < 8; nt++)
                        BH[nt] = bh[(ks * 16 + 8 * nh + nt) * 32];
                    const float2 v0 = *(const float2*)(stS + ra * 132 + 16 * ks + 2 * q);
                    const float2 v1 = *(const float2*)(stS + rb * 132 + 16 * ks + 2 * q);
                    const float2 v2 = *(const float2*)(stS + ra * 132 + 16 * ks + 8 + 2 * q);
                    const float2 v3 = *(const float2*)(stS + rb * 132 + 16 * ks + 8 + 2 * q);
                    uint32_t aH[4], aL[4];
                    split2(v0.x, v0.y, aH[0], aL[0]);
                    split2(v1.x, v1.y, aH[1], aL[1]);
                    split2(v2.x, v2.y, aH[2], aL[2]);
                    split2(v3.x, v3.y, aH[3], aL[3]);
                    #pragma unroll
                    for (int nt = 0; nt < 8; nt++) mma16816(c[nt], aH, BH[nt].x, BH[nt].y);
                    #pragma unroll
                    for (int nt = 0; nt < 8; nt++) mma16816(c[nt], aL, BH[nt].x, BH[nt].y);
                    #pragma unroll
                    for (int nt = 0; nt < 8; nt++) mma16816(c[nt], aH, BL[nt].x, BL[nt].y);
                }
            } else {
                const u64* srcS = ss ? st_xx : st_x;
                const float* Wl = (l == 0) ? W1 : (l == 1) ? W2 : W3;
                #pragma unroll
                for (int n = 0; n < 4; n++)
                    #pragma unroll
                    for (int p = 0; p < 8; p++) acc[n][p] = 0ull;
                #pragma unroll 4
                for (int k = 0; k < 128; k++) {
                    const float2 wa = __ldg((const float2*)(Wl + k * 128 + 2 * lane));
                    const float2 wb = __ldg((const float2*)(Wl + k * 128 + 64 + 2 * lane));
                    const u64 w_[4] = { pk2(wa.x, wa.x), pk2(wa.y, wa.y),
                                        pk2(wb.x, wb.x), pk2(wb.y, wb.y) };
                    const u64* rp = srcS + k * 18 + 8 * h;
                    const ulonglong2 u0 = *(const ulonglong2*)(rp);
                    const ulonglong2 u1 = *(const ulonglong2*)(rp + 2);
                    const ulonglong2 u2 = *(const ulonglong2*)(rp + 4);
                    const ulonglong2 u3 = *(const ulonglong2*)(rp + 6);
                    const u64 v_[8] = { u0.x, u0.y, u1.x, u1.y, u2.x, u2.y, u3.x, u3.y };
                    #pragma unroll
                    for (int n = 0; n < 4; n++)
                        #pragma unroll
                        for (int p = 0; p < 8; p++) fma2(acc[n][p], w_[n], v_[p]);
                }
            }
            __syncthreads();

            // ---- phase A: a-warps activate+publish; x-warps stash raw zx ----
            const float* bb = (l == 0) ? b1 : (l == 1) ? b2 : b3;
            if (isT && ts == 0) {
                float d0 = 0.f, d1 = 0.f;
                #pragma unroll
                for (int nt = 0; nt < 8; nt++) {
                    const int col = 64 * nh + 8 * nt + 2 * q;
                    const float bv0 = __ldg(bb + col), bv1 = __ldg(bb + col + 1);
                    const float a00 = tanhf_fast(c[nt][0] + bv0);
                    const float a01 = tanhf_fast(c[nt][1] + bv1);
                    const float a10 = tanhf_fast(c[nt][2] + bv0);
                    const float a11 = tanhf_fast(c[nt][3] + bv1);
                    *(float2*)(st_a + ra * 132 + col) = make_float2(a00, a01);
                    *(float2*)(st_a + rb * 132 + col) = make_float2(a10, a11);
                    if (last) {
                        const float w40 = __ldg(W4 + col), w41 = __ldg(W4 + col + 1);
                        d0 = fmaf(w40, a00, fmaf(w41, a01, d0));
                        d1 = fmaf(w40, a10, fmaf(w41, a11, d1));
                    }
                }
                if (last) {
                    d0 += __shfl_xor_sync(0xffffffffu, d0, 1);
                    d0 += __shfl_xor_sync(0xffffffffu, d0, 2);
                    d1 += __shfl_xor_sync(0xffffffffu, d1, 1);
                    d1 += __shfl_xor_sync(0xffffffffu, d1, 2);
                    if (q == 0) { sout[nh * 32 + ra] = d0; sout[nh * 32 + rb] = d1; }
                }
            } else if (!isT && ss == 0) {
                u64* z = zxscr + (h * 32 + lane) * 32;
                #pragma unroll
                for (int n = 0; n < 4; n++)
                    #pragma unroll
                    for (int p = 0; p < 8; p++) z[n * 8 + p] = acc[n][p];
            }
            __syncthreads();

            // ---- phase B: couplings ----
            if (isT && ts == 1) {
                float d0 = 0.f, d1 = 0.f;
                #pragma unroll
                for (int nt = 0; nt < 8; nt++) {
                    const int col = 64 * nh + 8 * nt + 2 * q;
                    const float2 aA = *(const float2*)(st_a + ra * 132 + col);
                    const float2 aB = *(const float2*)(st_a + rb * 132 + col);
                    const float t00 = (1.0f - aA.x * aA.x) * c[nt][0];
                    const float t01 = (1.0f - aA.y * aA.y) * c[nt][1];
                    const float t10 = (1.0f - aB.x * aB.x) * c[nt][2];
                    const float t11 = (1.0f - aB.y * aB.y) * c[nt][3];
                    if (!last) {
                        *(float2*)(st_t + ra * 132 + col) = make_float2(t00, t01);
                        *(float2*)(st_t + rb * 132 + col) = make_float2(t10, t11);
                    } else {
                        const float w40 = __ldg(W4 + col), w41 = __ldg(W4 + col + 1);
                        d0 = fmaf(w40, t00, fmaf(w41, t01, d0));
                        d1 = fmaf(w40, t10, fmaf(w41, t11, d1));
                    }
                }
                if (last) {
                    d0 += __shfl_xor_sync(0xffffffffu, d0, 1);
                    d0 += __shfl_xor_sync(0xffffffffu, d0, 2);
                    d1 += __shfl_xor_sync(0xffffffffu, d1, 1);
                    d1 += __shfl_xor_sync(0xffffffffu, d1, 2);
                    if (q == 0) { sout[64 + nh * 32 + ra] = d0; sout[64 + nh * 32 + rb] = d1; }
                }
            } else if (!isT) {
                const u64* z = zxscr + (h * 32 + lane) * 32;
                float sA[8], sB[8];
                #pragma unroll
                for (int p = 0; p < 8; p++) { sA[p] = 0.f; sB[p] = 0.f; }
                #pragma unroll
                for (int n = 0; n < 4; n++) {
                    const int j = jm[n];
                    const float w4 = last ? __ldg(W4 + j) : 0.f;
                    #pragma unroll
                    for (int p = 0; p < 8; p++) {
                        const int ptp = 8 * h + p, pt0 = 2 * ptp;
                        const float a0 = st_a[pt0 * 132 + j];
                        const float a1 = st_a[(pt0 + 1) * 132 + j];
                        const float p0 = 1.0f - a0 * a0, p1 = 1.0f - a1 * a1;
                        float o0, o1;
                        if (ss == 0) {
                            float z0, z1; upk2(acc[n][p], z0, z1);
                            o0 = p0 * z0; o1 = p1 * z1;
                        } else {
                            float zx0, zx1, w0, w1;
                            upk2(z[n * 8 + p], zx0, zx1);
                            upk2(acc[n][p], w0, w1);
                            o0 = p0 * fmaf(-2.0f * a0 * zx0, zx0, w0);
                            o1 = p1 * fmaf(-2.0f * a1 * zx1, zx1, w1);
                        }
                        if (!last) {
                            float* dst = ss ? fxx : fx;
                            dst[j * 36 + 2 * ptp]     = o0;
                            dst[j * 36 + 2 * ptp + 1] = o1;
                        } else {
                            sA[p] = fmaf(w4, o0, sA[p]);
                            sB[p] = fmaf(w4, o1, sB[p]);
                        }
                    }
                }
                if (last) {
                    #pragma unroll
                    for (int p = 0; p < 8; p++) {
                        #pragma unroll
                        for (int off = 16; off > 0; off >>= 1) {
                            sA[p] += __shfl_down_sync(0xffffffffu, sA[p], off);
                            sB[p] += __shfl_down_sync(0xffffffffu, sB[p], off);
                        }
                    }
                    if (lane == 0) {
                        #pragma unroll
                        for (int p = 0; p < 8; p++) {
                            sout[128 + ss * 32 + 16 * h + 2 * p]     = sA[p];
                            sout[128 + ss * 32 + 16 * h + 2 * p + 1] = sB[p];
                        }
                    }
                }
            }
            __syncthreads();
        }

        // ---- final combine (warp 0) ----
        if (wid == 0) {
            const int row = lane;
            const float u   = sout[row] + sout[32 + row] + b4v;
            const float ut  = sout[64 + row] + sout[96 + row];
            const float ux  = sout[128 + row];
            const float uxx = sout[160 + row];
            out[tile * 32 + row] = (tile < TEQ) ? (fmaf(u, ux, ut) - NU * uxx) : u;
        }
        __syncthreads();
    }
}

extern "C" void kernel_launch(void* const* d_in, const int* in_sizes, int n_in,
                              void* d_out, int out_size)
{
    const float* tx_eq   = (const float*)d_in[0];
    const float* tx_init = (const float*)d_in[1];
    const float* tx_bnd  = (const float*)d_in[2];
    const float* W0 = (const float*)d_in[3];
    const float* b0 = (const float*)d_in[4];
    const float* W1 = (const float*)d_in[5];
    const float* b1 = (const float*)d_in[6];
    const float* W2 = (const float*)d_in[7];
    const float* b2 = (const float*)d_in[8];
    const float* W3 = (const float*)d_in[9];
    const float* b3 = (const float*)d_in[10];
    const float* W4 = (const float*)d_in[11];
    const float* b4 = (const float*)d_in[12];
    float* out = (float*)d_out;

    prep_kernel<<<48, 256>>>(W1, W2, W3);

    cudaFuncSetAttribute(pinn_hy, cudaFuncAttributeMaxDynamicSharedMemorySize, SMEM_BYTES);
    int sms = 148;
    cudaDeviceGetAttribute(&sms, cudaDevAttrMultiProcessorCount, 0);
    if (sms > NTILES) sms = NTILES;

    pinn_hy<<<sms, 384, SMEM_BYTES>>>(tx_eq, tx_init, tx_bnd,
        W0, b0, W1, b1, W2, b2, W3, b3, W4, b4, out);
}

// round 15
// speedup vs baseline: 1.5105x; 1.5105x over previous
#include <cuda_runtime.h>
#include <cuda_bf16.h>
#include <stdint.h>

#define NTILES 4352          // 139264 / 32 points
#define TEQ    4096
#define TIB    4224
#define NU     0.0031830988618379067154f
typedef unsigned long long u64;

// W1..W3 bf16 fragments, h and l splits: [l][ks][nt][lane] -> uint2{b0,b1}
__device__ uint2 g_wfH[12288];
__device__ uint2 g_wfL[12288];

__device__ __forceinline__ uint32_t pkbf(float lo, float hi) {
    uint32_t r; asm("cvt.rn.bf16x2.f32 %0, %1, %2;" : "=r"(r) : "f"(hi), "f"(lo)); return r;
}
__device__ __forceinline__ void split2(float v0, float v1, uint32_t& h, uint32_t& l) {
    h = pkbf(v0, v1);
    float h0 = __uint_as_float(h << 16);
    float h1 = __uint_as_float(h & 0xffff0000u);
    l = pkbf(v0 - h0, v1 - h1);
}
__device__ __forceinline__ u64 pk2(float lo, float hi) {
    u64 r; asm("mov.b64 %0, {%1, %2};" : "=l"(r) : "f"(lo), "f"(hi)); return r;
}
__device__ __forceinline__ void upk2(u64 v, float& lo, float& hi) {
    asm("mov.b64 {%0, %1}, %2;" : "=f"(lo), "=f"(hi) : "l"(v));
}
__device__ __forceinline__ void fma2(u64& d, u64 a, u64 b) {
    asm("fma.rn.f32x2 %0, %1, %2, %0;" : "+l"(d) : "l"(a), "l"(b));
}
__device__ __forceinline__ float tanhf_fast(float z) {
    float e = __expf(2.0f * z);
    return __fdividef(e - 1.0f, e + 1.0f);
}
__device__ __forceinline__ void mma16816(float* c, const uint32_t* a, uint32_t b0, uint32_t b1) {
    asm volatile(
        "mma.sync.aligned.m16n8k16.row.col.f32.bf16.bf16.f32 "
        "{%0,%1,%2,%3}, {%4,%5,%6,%7}, {%8,%9}, {%0,%1,%2,%3};"
        : "+f"(c[0]), "+f"(c[1]), "+f"(c[2]), "+f"(c[3])
        : "r"(a[0]), "r"(a[1]), "r"(a[2]), "r"(a[3]), "r"(b0), "r"(b1));
}

__global__ void prep_kernel(const float* __restrict__ W1,
                            const float* __restrict__ W2,
                            const float* __restrict__ W3)
{
    const int gt = blockIdx.x * blockDim.x + threadIdx.x;
    const int lane = gt & 31, wi = gt >> 5;
    const int nt = wi & 15, ks = (wi >> 4) & 7, l = wi >> 7;
    const float* W = (l == 0) ? W1 : (l == 1) ? W2 : W3;
    const int j = nt * 8 + (lane >> 2), k0 = ks * 16 + 2 * (lane & 3);
    uint32_t h0, l0, h1, l1;
    split2(W[k0 * 128 + j], W[(k0 + 1) * 128 + j], h0, l0);
    split2(W[(k0 + 8) * 128 + j], W[(k0 + 9) * 128 + j], h1, l1);
    g_wfH[wi * 32 + lane] = make_uint2(h0, h1);
    g_wfL[wi * 32 + lane] = make_uint2(l0, l1);
}

// smem: whS (ks 0..5 only) 73728 | 5 state bufs 84480 | sWtail 49152
#define ST_STRIDE 132
#define ST_FLOATS 4224
#define OFF_ST    73728
#define OFF_WT    158208
#define SMEM_BYTES 207360

extern __shared__ char smem_raw[];

__global__ __launch_bounds__(512, 1)
void pinn_mma(const float* __restrict__ tx_eq, const float* __restrict__ tx_init,
              const float* __restrict__ tx_bnd,
              const float* __restrict__ W0, const float* __restrict__ b0,
              const float* __restrict__ W1, const float* __restrict__ b1,
              const float* __restrict__ W2, const float* __restrict__ b2,
              const float* __restrict__ W3, const float* __restrict__ b3,
              const float* __restrict__ W4, const float* __restrict__ b4,
              float* __restrict__ out)
{
    uint2*  whS    = (uint2*)smem_raw;
    float*  stf    = (float*)(smem_raw + OFF_ST);
    float*  st0    = stf;                  // a
    float*  st1    = stf + ST_FLOATS;      // at
    float*  st2    = stf + 2 * ST_FLOATS;  // raw zx scratch
    float*  st3    = stf + 3 * ST_FLOATS;  // axx
    float*  st4    = stf + 4 * ST_FLOATS;  // ax
    float*  sWtail = (float*)(smem_raw + OFF_WT);

    const int tid  = threadIdx.x;
    const int lane = tid & 31;
    const int wid  = tid >> 5;        // 0..15
    const int R    = wid & 1;
    const int s    = (wid >> 1) & 3;  // state
    const int nh   = wid >> 3;        // N-half
    const int g    = lane >> 2;
    const int q    = lane & 3;
    const int ra   = 16 * R + g;
    const int rb   = ra + 8;

    float* stS = (s == 0) ? st0 : (s == 1) ? st1 : (s == 2) ? st4 : st3;

    // weights into smem: bf16 frags for ks 0..5, fp32 tail rows 96..127
    for (int i = tid; i < 9216; i += 512)
        whS[i] = g_wfH[(i / 3072) * 4096 + (i % 3072)];
    for (int i = tid; i < 12288; i += 512) {
        const int l = i >> 12, r = i & 4095;
        const float* Wl = (l == 0) ? W1 : (l == 1) ? W2 : W3;
        sWtail[i] = Wl[12288 + r];
    }
    const float b4v = __ldg(b4);
    __syncthreads();

    for (int tile = blockIdx.x; tile < NTILES; tile += gridDim.x) {
        const float2* src;
        if (tile < TEQ)      src = (const float2*)tx_eq  + tile * 32;
        else if (tile < TIB) src = (const float2*)tx_init + (tile - TEQ) * 32;
        else                 src = (const float2*)tx_bnd  + (tile - TIB) * 32;

        const float2 Pa = __ldg(src + ra);
        const float2 Pb = __ldg(src + rb);

        // ---- layer 0 seeds: each warp its state, its rows/cols ----
        #pragma unroll
        for (int nt = 0; nt < 8; nt++) {
            float vA[2], vB[2];
            #pragma unroll
            for (int m = 0; m < 2; m++) {
                const int col = 64 * nh + 8 * nt + 2 * q + m;
                const float wt = __ldg(W0 + col);
                const float wx = __ldg(W0 + 128 + col);
                const float bb = __ldg(b0 + col);
                const float za = fmaf(wt, Pa.x, fmaf(wx, Pa.y, bb));
                const float zb = fmaf(wt, Pb.x, fmaf(wx, Pb.y, bb));
                const float a0 = tanhf_fast(za), a1 = tanhf_fast(zb);
                const float p0 = 1.0f - a0 * a0, p1 = 1.0f - a1 * a1;
                if (s == 0)      { vA[m] = a0;       vB[m] = a1; }
                else if (s == 1) { vA[m] = p0 * wt;  vB[m] = p1 * wt; }
                else if (s == 2) { vA[m] = p0 * wx;  vB[m] = p1 * wx; }
                else             { vA[m] = -2.0f * a0 * p0 * wx * wx;
                                   vB[m] = -2.0f * a1 * p1 * wx * wx; }
            }
            const int col0 = 64 * nh + 8 * nt + 2 * q;
            *(float2*)(stS + ra * ST_STRIDE + col0) = make_float2(vA[0], vA[1]);
            *(float2*)(stS + rb * ST_STRIDE + col0) = make_float2(vB[0], vB[1]);
        }
        __syncthreads();

        // ---- 3 hidden layers ----
        #pragma unroll 1
        for (int l = 0; l < 3; l++) {
            float c[8][4];
            #pragma unroll
            for (int nt = 0; nt < 8; nt++) {
                c[nt][0] = 0.f; c[nt][1] = 0.f; c[nt][2] = 0.f; c[nt][3] = 0.f;
            }
            // === tensor part: K 0..95 (3-term bf16 split) ===
            {
                const uint2* bh  = whS + l * 3072 + lane;
                const uint2* blg = g_wfL + l * 4096 + lane;
                #pragma unroll
                for (int ks = 0; ks < 6; ks++) {
                    uint2 BL[8], BH[8];
                    #pragma unroll
                    for (int nt = 0; nt < 8; nt++)
                        BL[nt] = __ldg(blg + (ks * 16 + 8 * nh + nt) * 32);
                    #pragma unroll
                    for (int nt = 0; nt < 8; nt++)
                        BH[nt] = bh[(ks * 16 + 8 * nh + nt) * 32];
                    const float2 v0 = *(const float2*)(stS + ra * ST_STRIDE + 16 * ks + 2 * q);
                    const float2 v1 = *(const float2*)(stS + rb * ST_STRIDE + 16 * ks + 2 * q);
                    const float2 v2 = *(const float2*)(stS + ra * ST_STRIDE + 16 * ks + 8 + 2 * q);
                    const float2 v3 = *(const float2*)(stS + rb * ST_STRIDE + 16 * ks + 8 + 2 * q);
                    uint32_t aH[4], aL[4];
                    split2(v0.x, v0.y, aH[0], aL[0]);
                    split2(v1.x, v1.y, aH[1], aL[1]);
                    split2(v2.x, v2.y, aH[2], aL[2]);
                    split2(v3.x, v3.y, aH[3], aL[3]);
                    #pragma unroll
                    for (int nt = 0; nt < 8; nt++) mma16816(c[nt], aH, BH[nt].x, BH[nt].y);
                    #pragma unroll
                    for (int nt = 0; nt < 8; nt++) mma16816(c[nt], aL, BH[nt].x, BH[nt].y);
                    #pragma unroll
                    for (int nt = 0; nt < 8; nt++) mma16816(c[nt], aH, BL[nt].x, BL[nt].y);
                }
            }
            // === FMA-pipe part: K 96..127, exact fp32 (col-pair packed) ===
            {
                u64 t2[8][2];
                #pragma unroll
                for (int nt = 0; nt < 8; nt++) { t2[nt][0] = 0ull; t2[nt][1] = 0ull; }
                const float* wt = sWtail + l * 4096 + 64 * nh + 2 * q;
                #pragma unroll 8
                for (int k = 0; k < 32; k++) {
                    const float sva = stS[ra * ST_STRIDE + 96 + k];
                    const float svb = stS[rb * ST_STRIDE + 96 + k];
                    const u64 sa = pk2(sva, sva);
                    const u64 sb = pk2(svb, svb);
                    const float* wk = wt + k * 128;
                    #pragma unroll
                    for (int nt = 0; nt < 8; nt++) {
                        const u64 w2 = *(const u64*)(wk + 8 * nt);
                        fma2(t2[nt][0], w2, sa);
                        fma2(t2[nt][1], w2, sb);
                    }
                }
                #pragma unroll
                for (int nt = 0; nt < 8; nt++) {
                    float lo, hi;
                    upk2(t2[nt][0], lo, hi); c[nt][0] += lo; c[nt][1] += hi;
                    upk2(t2[nt][1], lo, hi); c[nt][2] += lo; c[nt][3] += hi;
                }
            }
            __syncthreads();   // all reads of state buffers done before rewrites

            const float* bb = (l == 0) ? b1 : (l == 1) ? b2 : b3;
            // phase A: s0 activates + publishes a; s2 publishes raw zx
            if (s == 0) {
                #pragma unroll
                for (int nt = 0; nt < 8; nt++) {
                    const int col0 = 64 * nh + 8 * nt + 2 * q;
                    const float bv0 = __ldg(bb + col0);
                    const float bv1 = __ldg(bb + col0 + 1);
                    const float a00 = tanhf_fast(c[nt][0] + bv0);
                    const float a01 = tanhf_fast(c[nt][1] + bv1);
                    const float a10 = tanhf_fast(c[nt][2] + bv0);
                    const float a11 = tanhf_fast(c[nt][3] + bv1);
                    *(float2*)(st0 + ra * ST_STRIDE + col0) = make_float2(a00, a01);
                    *(float2*)(st0 + rb * ST_STRIDE + col0) = make_float2(a10, a11);
                }
            } else if (s == 2) {
                #pragma unroll
                for (int nt = 0; nt < 8; nt++) {
                    const int col0 = 64 * nh + 8 * nt + 2 * q;
                    *(float2*)(st2 + ra * ST_STRIDE + col0) = make_float2(c[nt][0], c[nt][1]);
                    *(float2*)(st2 + rb * ST_STRIDE + col0) = make_float2(c[nt][2], c[nt][3]);
                }
            }
            __syncthreads();
            // phase B: derivative couplings
            if (s != 0) {
                #pragma unroll
                for (int nt = 0; nt < 8; nt++) {
                    const int col0 = 64 * nh + 8 * nt + 2 * q;
                    const float2 aA = *(const float2*)(st0 + ra * ST_STRIDE + col0);
                    const float2 aB = *(const float2*)(st0 + rb * ST_STRIDE + col0);
                    const float p00 = 1.0f - aA.x * aA.x, p01 = 1.0f - aA.y * aA.y;
                    const float p10 = 1.0f - aB.x * aB.x, p11 = 1.0f - aB.y * aB.y;
                    float o0, o1, o2, o3;
                    if (s == 3) {
                        const float2 xA = *(const float2*)(st2 + ra * ST_STRIDE + col0);
                        const float2 xB = *(const float2*)(st2 + rb * ST_STRIDE + col0);
                        o0 = p00 * fmaf(-2.0f * aA.x * xA.x, xA.x, c[nt][0]);
                        o1 = p01 * fmaf(-2.0f * aA.y * xA.y, xA.y, c[nt][1]);
                        o2 = p10 * fmaf(-2.0f * aB.x * xB.x, xB.x, c[nt][2]);
                        o3 = p11 * fmaf(-2.0f * aB.y * xB.y, xB.y, c[nt][3]);
                    } else {
                        o0 = p00 * c[nt][0]; o1 = p01 * c[nt][1];
                        o2 = p10 * c[nt][2]; o3 = p11 * c[nt][3];
                    }
                    float* dst = (s == 1) ? st1 : (s == 2) ? st4 : st3;
                    *(float2*)(dst + ra * ST_STRIDE + col0) = make_float2(o0, o1);
                    *(float2*)(dst + rb * ST_STRIDE + col0) = make_float2(o2, o3);
                }
            }
            __syncthreads();
        }

        // ---- layer 4: warp wid reduces rows 2wid, 2wid+1 over all states ----
        {
            float acc[2][4];
            #pragma unroll
            for (int r = 0; r < 2; r++)
                #pragma unroll
                for (int k = 0; k < 4; k++) acc[r][k] = 0.f;
            #pragma unroll
            for (int m = 0; m < 4; m++) {
                const int j = lane + 32 * m;
                const float w4 = __ldg(W4 + j);
                #pragma unroll
                for (int r = 0; r < 2; r++) {
                    const int row = 2 * wid + r;
                    acc[r][0] = fmaf(w4, st0[row * ST_STRIDE + j], acc[r][0]);
                    acc[r][1] = fmaf(w4, st1[row * ST_STRIDE + j], acc[r][1]);
                    acc[r][2] = fmaf(w4, st4[row * ST_STRIDE + j], acc[r][2]);
                    acc[r][3] = fmaf(w4, st3[row * ST_STRIDE + j], acc[r][3]);
                }
            }
            #pragma unroll
            for (int off = 16; off > 0; off >>= 1)
                #pragma unroll
                for (int r = 0; r < 2; r++)
                    #pragma unroll
                    for (int k = 0; k < 4; k++)
                        acc[r][k] += __shfl_down_sync(0xffffffffu, acc[r][k], off);
            if (lane == 0) {
                #pragma unroll
                for (int r = 0; r < 2; r++) {
                    const float u   = acc[r][0] + b4v;
                    const float ut  = acc[r][1];
                    const float ux  = acc[r][2];
                    const float uxx = acc[r][3];
                    out[tile * 32 + 2 * wid + r] =
                        (tile < TEQ) ? (fmaf(u, ux, ut) - NU * uxx) : u;
                }
            }
        }
        __syncthreads();
    }
}

extern "C" void kernel_launch(void* const* d_in, const int* in_sizes, int n_in,
                              void* d_out, int out_size)
{
    const float* tx_eq   = (const float*)d_in[0];
    const float* tx_init = (const float*)d_in[1];
    const float* tx_bnd  = (const float*)d_in[2];
    const float* W0 = (const float*)d_in[3];
    const float* b0 = (const float*)d_in[4];
    const float* W1 = (const float*)d_in[5];
    const float* b1 = (const float*)d_in[6];
    const float* W2 = (const float*)d_in[7];
    const float* b2 = (const float*)d_in[8];
    const float* W3 = (const float*)d_in[9];
    const float* b3 = (const float*)d_in[10];
    const float* W4 = (const float*)d_in[11];
    const float* b4 = (const float*)d_in[12];
    float* out = (float*)d_out;

    prep_kernel<<<48, 256>>>(W1, W2, W3);

    cudaFuncSetAttribute(pinn_mma, cudaFuncAttributeMaxDynamicSharedMemorySize, SMEM_BYTES);
    int sms = 148;
    cudaDeviceGetAttribute(&sms, cudaDevAttrMultiProcessorCount, 0);
    if (sms > NTILES) sms = NTILES;

    pinn_mma<<<sms, 512, SMEM_BYTES>>>(tx_eq, tx_init, tx_bnd,
        W0, b0, W1, b1, W2, b2, W3, b3, W4, b4, out);
}